// round 10
// baseline (speedup 1.0000x reference)
#include <cuda_runtime.h>

#define DIM 64
#define NNODES_MAX 100032
#define NEDGES_MAX 1250000
#define SCAN_CHUNK 1024

// ---- scratch (device globals; device-code references only) ----
__device__ __align__(16) float g_hs[NNODES_MAX * DIM];    // (x @ W^T) * dis[row]
__device__ __align__(16) float g_bufA[NNODES_MAX * DIM];
__device__ __align__(16) float g_bufB[NNODES_MAX * DIM];
__device__ __align__(16) float g_dis[NNODES_MAX];
__device__ int   g_cnt[NNODES_MAX];
__device__ int   g_rowptr[NNODES_MAX + 1];
__device__ int   g_cursor[NNODES_MAX];
__device__ int   g_csr_src[NEDGES_MAX];
__device__ int   g_bsums[256];
__device__ __align__(16) float g_psum[256 * DIM];
__device__ __align__(16) float g_psq[256 * DIM];
__device__ __align__(16) float g_scale[DIM];
__device__ __align__(16) float g_shift[DIM];
__device__ int   g_is64;

// edge_index may be int32 (JAX x64 disabled coerces int64->int32) or true int64.
// elem is the logical element index in [0, 2E).
__device__ __forceinline__ int load_edge(const int* ei32, int is64, long long elem) {
    if (is64) return (int)(((const long long*)ei32)[elem]);
    return ei32[elem];
}

// If values are int64 (<2^31), every odd int32 word is a zero high-word.
__global__ void detect_dtype(const int* ei32) {
    if (blockIdx.x == 0 && threadIdx.x == 0) {
        int nz = 0;
        for (int i = 0; i < 512; i++) nz |= ei32[2 * i + 1];
        g_is64 = (nz == 0) ? 1 : 0;
    }
}

// ---------------- degree / CSR build ----------------
__global__ void zero_cnt(int n) {
    int i = blockIdx.x * blockDim.x + threadIdx.x;
    if (i < n) g_cnt[i] = 0;
}

__global__ void deg_count(const int* __restrict__ ei32, int E) {
    int e = blockIdx.x * blockDim.x + threadIdx.x;
    if (e >= E) return;
    int d = load_edge(ei32, g_is64, (long long)E + e);
    if ((unsigned)d < (unsigned)NNODES_MAX) atomicAdd(&g_cnt[d], 1);
}

__global__ void dis_compute(int n) {
    int i = blockIdx.x * blockDim.x + threadIdx.x;
    if (i < n) g_dis[i] = rsqrtf((float)(g_cnt[i] + 1));  // +1 self loop
}

__global__ __launch_bounds__(SCAN_CHUNK) void scanA(int n) {
    __shared__ int sh[SCAN_CHUNK];
    int t = threadIdx.x;
    int gid = blockIdx.x * SCAN_CHUNK + t;
    int v = (gid < n) ? g_cnt[gid] : 0;
    sh[t] = v;
    __syncthreads();
#pragma unroll
    for (int off = 1; off < SCAN_CHUNK; off <<= 1) {
        int a = (t >= off) ? sh[t - off] : 0;
        __syncthreads();
        sh[t] += a;
        __syncthreads();
    }
    if (gid < n) g_rowptr[gid] = sh[t] - v;
    if (t == SCAN_CHUNK - 1) g_bsums[blockIdx.x] = sh[t];
}

__global__ __launch_bounds__(128) void scanB(int nb) {
    __shared__ int sh[128];
    int t = threadIdx.x;
    int v = (t < nb) ? g_bsums[t] : 0;
    sh[t] = v;
    __syncthreads();
#pragma unroll
    for (int off = 1; off < 128; off <<= 1) {
        int a = (t >= off) ? sh[t - off] : 0;
        __syncthreads();
        sh[t] += a;
        __syncthreads();
    }
    if (t < nb) g_bsums[t] = sh[t] - v;
}

__global__ void scanC(int n, int E) {
    int gid = blockIdx.x * blockDim.x + threadIdx.x;
    if (gid < n) {
        int r = g_rowptr[gid] + g_bsums[gid >> 10];
        g_rowptr[gid] = r;
        g_cursor[gid] = r;
    }
    if (gid == 0) g_rowptr[n] = E;
}

__global__ void csr_fill(const int* __restrict__ ei32, int E) {
    int e = blockIdx.x * blockDim.x + threadIdx.x;
    if (e >= E) return;
    int is64 = g_is64;
    int s = load_edge(ei32, is64, (long long)e);
    int d = load_edge(ei32, is64, (long long)E + e);
    if ((unsigned)d >= (unsigned)NNODES_MAX) return;
    if ((unsigned)s >= (unsigned)NNODES_MAX) s = 0;
    int slot = atomicAdd(&g_cursor[d], 1);
    if (slot < NEDGES_MAX) g_csr_src[slot] = s;
}

// ---------------- GEMM: hs = (x@W^T)*dis ; y = hs*dis + b ----------------
// sel_in: 0 = external x, 1 = g_bufA, 2 = g_bufB.  sel_out: 1 = g_bufA, 2 = g_bufB.
__global__ __launch_bounds__(256) void gemm_kernel(
    int sel_in, int sel_out,
    const float* __restrict__ x_ext, const float* __restrict__ W,
    const float* __restrict__ b, int n)
{
    const float4* xsrc = (sel_in == 0) ? (const float4*)x_ext
                       : (sel_in == 1) ? (const float4*)g_bufA : (const float4*)g_bufB;
    float4* y4  = (sel_out == 1) ? (float4*)g_bufA : (float4*)g_bufB;
    float4* hs4 = (float4*)g_hs;

    __shared__ float Xs[64][68];
    __shared__ float Wsm[64][68];
    int tid  = threadIdx.x;
    int row0 = blockIdx.x * 64;

    for (int i = tid; i < 64 * 16; i += 256) {
        int r = i >> 4, c = i & 15;
        float4 v = ((const float4*)W)[i];
        Wsm[r][c * 4 + 0] = v.x; Wsm[r][c * 4 + 1] = v.y;
        Wsm[r][c * 4 + 2] = v.z; Wsm[r][c * 4 + 3] = v.w;
    }
    for (int i = tid; i < 64 * 16; i += 256) {
        int r = i >> 4, c = i & 15;
        float4 v = make_float4(0.f, 0.f, 0.f, 0.f);
        if (row0 + r < n) v = xsrc[(row0 + r) * 16 + c];
        Xs[r][c * 4 + 0] = v.x; Xs[r][c * 4 + 1] = v.y;
        Xs[r][c * 4 + 2] = v.z; Xs[r][c * 4 + 3] = v.w;
    }
    __syncthreads();

    int rg = tid >> 3, cg = tid & 7;
    int r0 = rg * 2, c0 = cg * 8;

    float acc[2][8];
#pragma unroll
    for (int i = 0; i < 2; i++)
#pragma unroll
        for (int j = 0; j < 8; j++) acc[i][j] = 0.f;

#pragma unroll
    for (int k4 = 0; k4 < 16; k4++) {
        float4 a0 = *(const float4*)&Xs[r0 + 0][k4 * 4];
        float4 a1 = *(const float4*)&Xs[r0 + 1][k4 * 4];
#pragma unroll
        for (int j = 0; j < 8; j++) {
            float4 w = *(const float4*)&Wsm[c0 + j][k4 * 4];
            acc[0][j] += a0.x * w.x; acc[0][j] += a0.y * w.y;
            acc[0][j] += a0.z * w.z; acc[0][j] += a0.w * w.w;
            acc[1][j] += a1.x * w.x; acc[1][j] += a1.y * w.y;
            acc[1][j] += a1.z * w.z; acc[1][j] += a1.w * w.w;
        }
    }

    float4 b0 = ((const float4*)b)[cg * 2 + 0];
    float4 b1 = ((const float4*)b)[cg * 2 + 1];

#pragma unroll
    for (int i = 0; i < 2; i++) {
        int row = row0 + r0 + i;
        if (row < n) {
            float di = g_dis[row];
            float4 h0 = make_float4(acc[i][0] * di, acc[i][1] * di, acc[i][2] * di, acc[i][3] * di);
            float4 h1 = make_float4(acc[i][4] * di, acc[i][5] * di, acc[i][6] * di, acc[i][7] * di);
            hs4[row * 16 + cg * 2 + 0] = h0;
            hs4[row * 16 + cg * 2 + 1] = h1;
            float4 y0 = make_float4(h0.x * di + b0.x, h0.y * di + b0.y, h0.z * di + b0.z, h0.w * di + b0.w);
            float4 y1 = make_float4(h1.x * di + b1.x, h1.y * di + b1.y, h1.z * di + b1.z, h1.w * di + b1.w);
            y4[row * 16 + cg * 2 + 0] = y0;
            y4[row * 16 + cg * 2 + 1] = y1;
        }
    }
}

// ---------------- gather: y[d] += dis[d] * sum_{e in CSR(d)} hs[src(e)] ----------------
// warp per destination node; lane handles 2 columns (float2).
__global__ __launch_bounds__(256) void gather_kernel(int sel_out, int n)
{
    const float2* hs2 = (const float2*)g_hs;
    float2* y2 = (sel_out == 1) ? (float2*)g_bufA : (float2*)g_bufB;

    int w = (blockIdx.x * 256 + threadIdx.x) >> 5;
    if (w >= n) return;
    int lane = threadIdx.x & 31;
    int beg = g_rowptr[w];
    int end = g_rowptr[w + 1];
    float ax = 0.f, ay = 0.f;
    for (int i = beg; i < end; i++) {
        int s = g_csr_src[i];
        float2 v = hs2[s * 32 + lane];
        ax += v.x; ay += v.y;
    }
    float dd = g_dis[w];
    int oi = w * 32 + lane;
    float2 o = y2[oi];
    o.x += ax * dd; o.y += ay * dd;
    y2[oi] = o;
}

// ---------------- BatchNorm (deterministic two-pass); input g_bufA ----------------
__global__ __launch_bounds__(256) void bn_partial(int n) {
    int col = threadIdx.x & 63;
    int sub = threadIdx.x >> 6;
    float s = 0.f, sq = 0.f;
    for (int r = blockIdx.x * 4 + sub; r < n; r += 256 * 4) {
        float v = g_bufA[r * 64 + col];
        s += v; sq += v * v;
    }
    __shared__ float ss[4][64], sqq[4][64];
    ss[sub][col] = s; sqq[sub][col] = sq;
    __syncthreads();
    if (sub == 0) {
        s  = ss[0][col] + ss[1][col] + ss[2][col] + ss[3][col];
        sq = sqq[0][col] + sqq[1][col] + sqq[2][col] + sqq[3][col];
        g_psum[blockIdx.x * 64 + col] = s;
        g_psq[blockIdx.x * 64 + col]  = sq;
    }
}

__global__ void bn_final(const float* __restrict__ gamma, const float* __restrict__ beta, int n) {
    int c = threadIdx.x;
    if (c >= 64) return;
    float s = 0.f, sq = 0.f;
    for (int b = 0; b < 256; b++) {
        s  += g_psum[b * 64 + c];
        sq += g_psq[b * 64 + c];
    }
    float inv_n = 1.f / (float)n;
    float mean = s * inv_n;
    float var  = sq * inv_n - mean * mean;
    float sc = gamma[c] * rsqrtf(var + 1e-5f);
    g_scale[c] = sc;
    g_shift[c] = beta[c] - mean * sc;
}

__global__ __launch_bounds__(256) void bn_apply(float4* __restrict__ out, int n4) {
    int i = blockIdx.x * 256 + threadIdx.x;
    if (i >= n4) return;
    int c = i & 15;
    float4 v  = ((const float4*)g_bufA)[i];
    float4 sc = ((const float4*)g_scale)[c];
    float4 sh = ((const float4*)g_shift)[c];
    v.x = v.x * sc.x + sh.x;
    v.y = v.y * sc.y + sh.y;
    v.z = v.z * sc.z + sh.z;
    v.w = v.w * sc.w + sh.w;
    out[i] = v;
}

// ---------------- launch ----------------
extern "C" void kernel_launch(void* const* d_in, const int* in_sizes, int n_in,
                              void* d_out, int out_size) {
    const float* x     = (const float*)d_in[0];
    const int*   ei32  = (const int*)d_in[1];   // int32 or int64, detected on device
    const float* Ws    = (const float*)d_in[2];
    const float* bs    = (const float*)d_in[3];
    const float* gamma = (const float*)d_in[4];
    const float* beta  = (const float*)d_in[5];

    int n = in_sizes[0] / DIM;
    int E = in_sizes[1] / 2;

    int nb_n = (n + 255) / 256;
    int nb_e = (E + 255) / 256;
    int nchunks = (n + SCAN_CHUNK - 1) / SCAN_CHUNK;

    detect_dtype<<<1, 32>>>(ei32);

    // degrees + CSR
    zero_cnt<<<nb_n, 256>>>(n);
    deg_count<<<nb_e, 256>>>(ei32, E);
    dis_compute<<<nb_n, 256>>>(n);
    scanA<<<nchunks, SCAN_CHUNK>>>(n);
    scanB<<<1, 128>>>(nchunks);
    scanC<<<nb_n, 256>>>(n, E);
    csr_fill<<<nb_e, 256>>>(ei32, E);

    int gemm_blocks = (n + 63) / 64;
    int gath_blocks = (n * 32 + 255) / 256;

    // Layer 0: x -> bufA
    gemm_kernel<<<gemm_blocks, 256>>>(0, 1, x, Ws + 0 * DIM * DIM, bs + 0 * DIM, n);
    gather_kernel<<<gath_blocks, 256>>>(1, n);
    // Layer 1: bufA -> bufB
    gemm_kernel<<<gemm_blocks, 256>>>(1, 2, x, Ws + 1 * DIM * DIM, bs + 1 * DIM, n);
    gather_kernel<<<gath_blocks, 256>>>(2, n);
    // Layer 2: bufB -> bufA
    gemm_kernel<<<gemm_blocks, 256>>>(2, 1, x, Ws + 2 * DIM * DIM, bs + 2 * DIM, n);
    gather_kernel<<<gath_blocks, 256>>>(1, n);

    // BatchNorm -> d_out
    bn_partial<<<256, 256>>>(n);
    bn_final<<<1, 64>>>(gamma, beta, n);
    bn_apply<<<(n * 16 + 255) / 256, 256>>>((float4*)d_out, n * 16);
}

// round 12
// speedup vs baseline: 1.0064x; 1.0064x over previous
#include <cuda_runtime.h>

#define DIM 64
#define NNODES_MAX 100032
#define NEDGES_MAX 1250000
#define SCAN_CHUNK 1024

// ---- scratch (device globals; device-code references only) ----
__device__ __align__(16) float g_hs[NNODES_MAX * DIM];    // (x @ W^T) * dis[row]
__device__ __align__(16) float g_bufA[NNODES_MAX * DIM];
__device__ __align__(16) float g_bufB[NNODES_MAX * DIM];
__device__ __align__(16) float g_dis[NNODES_MAX];
__device__ int   g_cnt[NNODES_MAX];
__device__ int   g_rowptr[NNODES_MAX + 1];
__device__ int   g_cursor[NNODES_MAX];
__device__ int   g_csr_src[NEDGES_MAX];
__device__ int   g_bsums[256];
__device__ __align__(16) float g_psum[256 * DIM];
__device__ __align__(16) float g_psq[256 * DIM];
__device__ __align__(16) float g_scale[DIM];
__device__ __align__(16) float g_shift[DIM];
__device__ int   g_is64;

__device__ __forceinline__ int load_edge(const int* ei32, int is64, long long elem) {
    if (is64) return (int)(((const long long*)ei32)[elem]);
    return ei32[elem];
}

// fused: zero counters + dtype detect (warp 0 of block 0)
__global__ void prep_kernel(const int* __restrict__ ei32, int n) {
    int i = blockIdx.x * blockDim.x + threadIdx.x;
    if (i < n) g_cnt[i] = 0;
    if (blockIdx.x == 0 && threadIdx.x < 32) {
        int nz = 0;
        for (int k = threadIdx.x; k < 512; k += 32) nz |= ei32[2 * k + 1];
        unsigned any = __ballot_sync(0xffffffffu, nz != 0);
        if (threadIdx.x == 0) g_is64 = (any == 0) ? 1 : 0;
    }
}

__global__ void deg_count(const int* __restrict__ ei32, int E) {
    int e = blockIdx.x * blockDim.x + threadIdx.x;
    if (e >= E) return;
    int d = load_edge(ei32, g_is64, (long long)E + e);
    if ((unsigned)d < (unsigned)NNODES_MAX) atomicAdd(&g_cnt[d], 1);
}

// scanA: chunk-local exclusive scan + dis = rsqrt(deg+1) fused
__global__ __launch_bounds__(SCAN_CHUNK) void scanA(int n) {
    __shared__ int sh[SCAN_CHUNK];
    int t = threadIdx.x;
    int gid = blockIdx.x * SCAN_CHUNK + t;
    int v = (gid < n) ? g_cnt[gid] : 0;
    if (gid < n) g_dis[gid] = rsqrtf((float)(v + 1));
    sh[t] = v;
    __syncthreads();
#pragma unroll
    for (int off = 1; off < SCAN_CHUNK; off <<= 1) {
        int a = (t >= off) ? sh[t - off] : 0;
        __syncthreads();
        sh[t] += a;
        __syncthreads();
    }
    if (gid < n) g_rowptr[gid] = sh[t] - v;
    if (t == SCAN_CHUNK - 1) g_bsums[blockIdx.x] = sh[t];
}

__global__ __launch_bounds__(128) void scanB(int nb) {
    __shared__ int sh[128];
    int t = threadIdx.x;
    int v = (t < nb) ? g_bsums[t] : 0;
    sh[t] = v;
    __syncthreads();
#pragma unroll
    for (int off = 1; off < 128; off <<= 1) {
        int a = (t >= off) ? sh[t - off] : 0;
        __syncthreads();
        sh[t] += a;
        __syncthreads();
    }
    if (t < nb) g_bsums[t] = sh[t] - v;
}

__global__ void scanC(int n, int E) {
    int gid = blockIdx.x * blockDim.x + threadIdx.x;
    if (gid < n) {
        int r = g_rowptr[gid] + g_bsums[gid >> 10];
        g_rowptr[gid] = r;
        g_cursor[gid] = r;
    }
    if (gid == 0) g_rowptr[n] = E;
}

__global__ void csr_fill(const int* __restrict__ ei32, int E) {
    int e = blockIdx.x * blockDim.x + threadIdx.x;
    if (e >= E) return;
    int is64 = g_is64;
    int s = load_edge(ei32, is64, (long long)e);
    int d = load_edge(ei32, is64, (long long)E + e);
    if ((unsigned)d >= (unsigned)NNODES_MAX) return;
    if ((unsigned)s >= (unsigned)NNODES_MAX) s = 0;
    int slot = atomicAdd(&g_cursor[d], 1);
    if (slot < NEDGES_MAX) g_csr_src[slot] = s;
}

// ---------------- GEMM: hs = (x@W^T) * dis[row]  (no y output) ----------------
// sel_in: 0 = external x, 1 = g_bufA, 2 = g_bufB.
__global__ __launch_bounds__(256) void gemm_kernel(
    int sel_in, const float* __restrict__ x_ext, const float* __restrict__ W, int n)
{
    const float4* xsrc = (sel_in == 0) ? (const float4*)x_ext
                       : (sel_in == 1) ? (const float4*)g_bufA : (const float4*)g_bufB;
    float4* hs4 = (float4*)g_hs;

    __shared__ float Xs[64][68];
    __shared__ float Wsm[64][68];
    int tid  = threadIdx.x;
    int row0 = blockIdx.x * 64;

    for (int i = tid; i < 64 * 16; i += 256) {
        int r = i >> 4, c = i & 15;
        float4 v = ((const float4*)W)[i];
        Wsm[r][c * 4 + 0] = v.x; Wsm[r][c * 4 + 1] = v.y;
        Wsm[r][c * 4 + 2] = v.z; Wsm[r][c * 4 + 3] = v.w;
    }
    for (int i = tid; i < 64 * 16; i += 256) {
        int r = i >> 4, c = i & 15;
        float4 v = make_float4(0.f, 0.f, 0.f, 0.f);
        if (row0 + r < n) v = xsrc[(row0 + r) * 16 + c];
        Xs[r][c * 4 + 0] = v.x; Xs[r][c * 4 + 1] = v.y;
        Xs[r][c * 4 + 2] = v.z; Xs[r][c * 4 + 3] = v.w;
    }
    __syncthreads();

    int rg = tid >> 3, cg = tid & 7;
    int r0 = rg * 2, c0 = cg * 8;

    float acc[2][8];
#pragma unroll
    for (int i = 0; i < 2; i++)
#pragma unroll
        for (int j = 0; j < 8; j++) acc[i][j] = 0.f;

#pragma unroll
    for (int k4 = 0; k4 < 16; k4++) {
        float4 a0 = *(const float4*)&Xs[r0 + 0][k4 * 4];
        float4 a1 = *(const float4*)&Xs[r0 + 1][k4 * 4];
#pragma unroll
        for (int j = 0; j < 8; j++) {
            float4 w = *(const float4*)&Wsm[c0 + j][k4 * 4];
            acc[0][j] += a0.x * w.x; acc[0][j] += a0.y * w.y;
            acc[0][j] += a0.z * w.z; acc[0][j] += a0.w * w.w;
            acc[1][j] += a1.x * w.x; acc[1][j] += a1.y * w.y;
            acc[1][j] += a1.z * w.z; acc[1][j] += a1.w * w.w;
        }
    }

#pragma unroll
    for (int i = 0; i < 2; i++) {
        int row = row0 + r0 + i;
        if (row < n) {
            float di = g_dis[row];
            hs4[row * 16 + cg * 2 + 0] = make_float4(acc[i][0] * di, acc[i][1] * di, acc[i][2] * di, acc[i][3] * di);
            hs4[row * 16 + cg * 2 + 1] = make_float4(acc[i][4] * di, acc[i][5] * di, acc[i][6] * di, acc[i][7] * di);
        }
    }
}

// ---------------- gather: y[d] = dis[d]*(sum_src hs[src] + hs[d]) + b ----------------
// warp per dst; coalesced index prefetch + shfl broadcast; 4 accumulator pairs.
__global__ __launch_bounds__(256) void gather_kernel(int sel_out, const float* __restrict__ b, int n)
{
    const float2* hs2 = (const float2*)g_hs;
    float2* y2 = (sel_out == 1) ? (float2*)g_bufA : (float2*)g_bufB;

    int w = (blockIdx.x * 256 + threadIdx.x) >> 5;
    if (w >= n) return;
    int lane = threadIdx.x & 31;
    int beg = g_rowptr[w];
    int end = g_rowptr[w + 1];

    float a0x = 0.f, a0y = 0.f, a1x = 0.f, a1y = 0.f;
    float a2x = 0.f, a2y = 0.f, a3x = 0.f, a3y = 0.f;

    for (int base = beg; base < end; base += 32) {
        int gi = base + lane;
        int idx = (gi < end) ? g_csr_src[gi] : 0;
        int cnt = end - base; if (cnt > 32) cnt = 32;
        int j = 0;
        for (; j + 4 <= cnt; j += 4) {
            int s0 = __shfl_sync(0xffffffffu, idx, j);
            int s1 = __shfl_sync(0xffffffffu, idx, j + 1);
            int s2 = __shfl_sync(0xffffffffu, idx, j + 2);
            int s3 = __shfl_sync(0xffffffffu, idx, j + 3);
            float2 v0 = hs2[s0 * 32 + lane];
            float2 v1 = hs2[s1 * 32 + lane];
            float2 v2 = hs2[s2 * 32 + lane];
            float2 v3 = hs2[s3 * 32 + lane];
            a0x += v0.x; a0y += v0.y;
            a1x += v1.x; a1y += v1.y;
            a2x += v2.x; a2y += v2.y;
            a3x += v3.x; a3y += v3.y;
        }
        for (; j < cnt; j++) {
            int s = __shfl_sync(0xffffffffu, idx, j);
            float2 v = hs2[s * 32 + lane];
            a0x += v.x; a0y += v.y;
        }
    }

    float2 hself = hs2[w * 32 + lane];      // self loop: hs[d]
    float dd = g_dis[w];
    float2 bv = ((const float2*)b)[lane];
    float2 o;
    o.x = (a0x + a1x + a2x + a3x + hself.x) * dd + bv.x;
    o.y = (a0y + a1y + a2y + a3y + hself.y) * dd + bv.y;
    y2[w * 32 + lane] = o;
}

// ---------------- BatchNorm (deterministic two-pass); input g_bufA ----------------
__global__ __launch_bounds__(256) void bn_partial(int n) {
    int col = threadIdx.x & 63;
    int sub = threadIdx.x >> 6;
    float s = 0.f, sq = 0.f;
    for (int r = blockIdx.x * 4 + sub; r < n; r += 256 * 4) {
        float v = g_bufA[r * 64 + col];
        s += v; sq += v * v;
    }
    __shared__ float ss[4][64], sqq[4][64];
    ss[sub][col] = s; sqq[sub][col] = sq;
    __syncthreads();
    if (sub == 0) {
        s  = ss[0][col] + ss[1][col] + ss[2][col] + ss[3][col];
        sq = sqq[0][col] + sqq[1][col] + sqq[2][col] + sqq[3][col];
        g_psum[blockIdx.x * 64 + col] = s;
        g_psq[blockIdx.x * 64 + col]  = sq;
    }
}

__global__ void bn_final(const float* __restrict__ gamma, const float* __restrict__ beta, int n) {
    int c = threadIdx.x;
    if (c >= 64) return;
    float s = 0.f, sq = 0.f;
    for (int b = 0; b < 256; b++) {
        s  += g_psum[b * 64 + c];
        sq += g_psq[b * 64 + c];
    }
    float inv_n = 1.f / (float)n;
    float mean = s * inv_n;
    float var  = sq * inv_n - mean * mean;
    float sc = gamma[c] * rsqrtf(var + 1e-5f);
    g_scale[c] = sc;
    g_shift[c] = beta[c] - mean * sc;
}

__global__ __launch_bounds__(256) void bn_apply(float4* __restrict__ out, int n4) {
    int i = blockIdx.x * 256 + threadIdx.x;
    if (i >= n4) return;
    int c = i & 15;
    float4 v  = ((const float4*)g_bufA)[i];
    float4 sc = ((const float4*)g_scale)[c];
    float4 sh = ((const float4*)g_shift)[c];
    v.x = v.x * sc.x + sh.x;
    v.y = v.y * sc.y + sh.y;
    v.z = v.z * sc.z + sh.z;
    v.w = v.w * sc.w + sh.w;
    out[i] = v;
}

// ---------------- launch ----------------
extern "C" void kernel_launch(void* const* d_in, const int* in_sizes, int n_in,
                              void* d_out, int out_size) {
    const float* x     = (const float*)d_in[0];
    const int*   ei32  = (const int*)d_in[1];
    const float* Ws    = (const float*)d_in[2];
    const float* bs    = (const float*)d_in[3];
    const float* gamma = (const float*)d_in[4];
    const float* beta  = (const float*)d_in[5];

    int n = in_sizes[0] / DIM;
    int E = in_sizes[1] / 2;

    int nb_n = (n + 255) / 256;
    int nb_e = (E + 255) / 256;
    int nchunks = (n + SCAN_CHUNK - 1) / SCAN_CHUNK;

    // CSR build
    prep_kernel<<<nb_n, 256>>>(ei32, n);
    deg_count<<<nb_e, 256>>>(ei32, E);
    scanA<<<nchunks, SCAN_CHUNK>>>(n);
    scanB<<<1, 128>>>(nchunks);
    scanC<<<nb_n, 256>>>(n, E);
    csr_fill<<<nb_e, 256>>>(ei32, E);

    int gemm_blocks = (n + 63) / 64;
    int gath_blocks = (n * 32 + 255) / 256;

    // Layer 0: x -> bufA
    gemm_kernel<<<gemm_blocks, 256>>>(0, x, Ws + 0 * DIM * DIM, n);
    gather_kernel<<<gath_blocks, 256>>>(1, bs + 0 * DIM, n);
    // Layer 1: bufA -> bufB
    gemm_kernel<<<gemm_blocks, 256>>>(1, x, Ws + 1 * DIM * DIM, n);
    gather_kernel<<<gath_blocks, 256>>>(2, bs + 1 * DIM, n);
    // Layer 2: bufB -> bufA
    gemm_kernel<<<gemm_blocks, 256>>>(2, x, Ws + 2 * DIM * DIM, n);
    gather_kernel<<<gath_blocks, 256>>>(1, bs + 2 * DIM, n);

    // BatchNorm -> d_out
    bn_partial<<<256, 256>>>(n);
    bn_final<<<1, 64>>>(gamma, beta, n);
    bn_apply<<<(n * 16 + 255) / 256, 256>>>((float4*)d_out, n * 16);
}